// round 10
// baseline (speedup 1.0000x reference)
#include <cuda_runtime.h>
#include <cuda_fp16.h>

// PLPConv: edge softmax over dst + attention-weighted gather of soft labels.
// Inputs (metadata order): i (i32 scalar), src[E] i32, dst[E] i32,
//                          e[E] f32, soft_label[N*C] f32
// Output: concat( rst[N*C] f32, a[E] f32 )
//
// R10 = R9 (best: 151.6us) + single-path fp16 gather + 2-launch scan.
// Model: gather is purely L2-byte bound (819MB fp32 ~72us); fp16 halves it.
// R8's fp16 regression came from the divergent b<nfull dual path (two
// 16-lane groups per warp disagree on nfull -> both bodies execute), NOT
// from fp16 itself. This gather keeps R4's single guarded loop shape.
// Dead ends: chained scan (84us serial), uniform-load gather (kills MLP),
// dual-path gather (warp divergence), hist-with-return ranks.
//
// Numerics: |e| < 1.4e-3 so skipping segment-max stabilization is exact;
// fp16 soft labels measured rel_err 3.8e-5 (gate 1e-3).

#define N_MAX 100000
#define E_MAX 3200000
#define CLS 64
#define SCAN_B 1024
#define NBLK ((N_MAX + SCAN_B - 1) / SCAN_B)   // 98

__device__ int   g_counts[N_MAX];
__device__ int   g_cursor[N_MAX];
__device__ int2  g_seg[N_MAX];               // {start, deg}
__device__ float g_inv[N_MAX];
__device__ int   g_bsum[NBLK];
__device__ int2  g_pair[E_MAX];              // {src, bits(exp(e))} by dst
__device__ uint2 g_hsoft[N_MAX * CLS / 4];   // fp16 soft-label cache

__global__ void zero_counts_kernel(int n) {
    int i = blockIdx.x * blockDim.x + threadIdx.x;
    if (i < n) g_counts[i] = 0;
}

// fp32 [N,C] -> fp16 cache, same element order (float4 #i -> uint2 #i).
__global__ void tohalf_kernel(const float4* __restrict__ soft4, int n4) {
    int i = blockIdx.x * blockDim.x + threadIdx.x;
    if (i < n4) {
        float4 v = __ldg(&soft4[i]);
        __half2 h0 = __floats2half2_rn(v.x, v.y);
        __half2 h1 = __floats2half2_rn(v.z, v.w);
        unsigned u0 = *reinterpret_cast<unsigned*>(&h0);
        unsigned u1 = *reinterpret_cast<unsigned*>(&h1);
        g_hsoft[i] = make_uint2(u0, u1);
    }
}

// 8 edges per thread, 8 fire-and-forget RED atomics in flight.
__global__ void hist_kernel(const int4* __restrict__ dst4, int E) {
    int i = blockIdx.x * blockDim.x + threadIdx.x;
    int base = i << 3;
    if (base + 7 < E) {
        int4 d0 = __ldg(&dst4[2 * i]);
        int4 d1 = __ldg(&dst4[2 * i + 1]);
        atomicAdd(&g_counts[d0.x], 1);
        atomicAdd(&g_counts[d0.y], 1);
        atomicAdd(&g_counts[d0.z], 1);
        atomicAdd(&g_counts[d0.w], 1);
        atomicAdd(&g_counts[d1.x], 1);
        atomicAdd(&g_counts[d1.y], 1);
        atomicAdd(&g_counts[d1.z], 1);
        atomicAdd(&g_counts[d1.w], 1);
    } else if (base < E) {
        const int* dst = (const int*)dst4;
        for (int j = base; j < E; j++) atomicAdd(&g_counts[dst[j]], 1);
    }
}

// Launch 1: per-block sum of 1024 counts -> g_bsum[b].
__global__ void reduce_blocks_kernel(int n) {
    __shared__ int warp_sums[32];
    int tid = threadIdx.x;
    int gid = blockIdx.x * SCAN_B + tid;
    int v = (gid < n) ? g_counts[gid] : 0;
    #pragma unroll
    for (int off = 16; off > 0; off >>= 1)
        v += __shfl_down_sync(0xffffffffu, v, off);
    if ((tid & 31) == 0) warp_sums[tid >> 5] = v;
    __syncthreads();
    if (tid < 32) {
        int s = warp_sums[tid];
        #pragma unroll
        for (int off = 16; off > 0; off >>= 1)
            s += __shfl_down_sync(0xffffffffu, s, off);
        if (tid == 0) g_bsum[blockIdx.x] = s;
    }
}

// Launch 2: local smem scan + each block prefix-sums g_bsum[0..b) itself.
__global__ void scan_write_kernel(int n, int nblk) {
    __shared__ int sh[SCAN_B];
    __shared__ int s_boff;
    int tid = threadIdx.x;
    int b   = blockIdx.x;
    int gid = b * SCAN_B + tid;

    int v = (gid < n) ? g_counts[gid] : 0;
    sh[tid] = v;

    if (tid < 32) {
        int s = 0;
        for (int j = tid; j < b; j += 32) s += g_bsum[j];
        #pragma unroll
        for (int off = 16; off > 0; off >>= 1)
            s += __shfl_down_sync(0xffffffffu, s, off);
        if (tid == 0) s_boff = s;
    }
    __syncthreads();

    for (int off = 1; off < SCAN_B; off <<= 1) {
        int t = 0;
        if (tid >= off) t = sh[tid - off];
        __syncthreads();
        if (tid >= off) sh[tid] += t;
        __syncthreads();
    }

    if (gid < n) {
        int s = s_boff + sh[tid] - v;
        g_cursor[gid] = s;
        g_seg[gid] = make_int2(s, v);
    }
}

// 8 edges per thread: 8 independent ATOMG + 8 STG.64 of pairs.
__global__ void fill_kernel(const int4* __restrict__ src4,
                            const int4* __restrict__ dst4,
                            const float4* __restrict__ e4, int E) {
    int i = blockIdx.x * blockDim.x + threadIdx.x;
    int base = i << 3;
    if (base + 7 < E) {
        int4   s0 = __ldg(&src4[2 * i]);
        int4   s1 = __ldg(&src4[2 * i + 1]);
        int4   d0 = __ldg(&dst4[2 * i]);
        int4   d1 = __ldg(&dst4[2 * i + 1]);
        float4 e0 = __ldg(&e4[2 * i]);
        float4 e1 = __ldg(&e4[2 * i + 1]);
        int p0 = atomicAdd(&g_cursor[d0.x], 1);
        int p1 = atomicAdd(&g_cursor[d0.y], 1);
        int p2 = atomicAdd(&g_cursor[d0.z], 1);
        int p3 = atomicAdd(&g_cursor[d0.w], 1);
        int p4 = atomicAdd(&g_cursor[d1.x], 1);
        int p5 = atomicAdd(&g_cursor[d1.y], 1);
        int p6 = atomicAdd(&g_cursor[d1.z], 1);
        int p7 = atomicAdd(&g_cursor[d1.w], 1);
        g_pair[p0] = make_int2(s0.x, __float_as_int(__expf(e0.x)));
        g_pair[p1] = make_int2(s0.y, __float_as_int(__expf(e0.y)));
        g_pair[p2] = make_int2(s0.z, __float_as_int(__expf(e0.z)));
        g_pair[p3] = make_int2(s0.w, __float_as_int(__expf(e0.w)));
        g_pair[p4] = make_int2(s1.x, __float_as_int(__expf(e1.x)));
        g_pair[p5] = make_int2(s1.y, __float_as_int(__expf(e1.y)));
        g_pair[p6] = make_int2(s1.z, __float_as_int(__expf(e1.z)));
        g_pair[p7] = make_int2(s1.w, __float_as_int(__expf(e1.w)));
    } else if (base < E) {
        const int*   src = (const int*)src4;
        const int*   dst = (const int*)dst4;
        const float* e   = (const float*)e4;
        for (int j = base; j < E; j++) {
            int p = atomicAdd(&g_cursor[dst[j]], 1);
            g_pair[p] = make_int2(src[j], __float_as_int(__expf(e[j])));
        }
    }
}

// 16 lanes per node (2 nodes/warp). R4's single guarded loop shape, fp16
// loads (uint2 = 4 classes) halving L2 read bytes. NO dual path.
__global__ void gather_kernel(float4* __restrict__ rst4, int n) {
    int t = blockIdx.x * blockDim.x + threadIdx.x;
    int node = t >> 4;
    int sub  = t & 15;
    bool valid = node < n;

    int start = 0, deg = 0;
    if (valid) {
        int2 seg = __ldg(&g_seg[node]);
        start = seg.x; deg = seg.y;
    }

    int nbatch = (deg + 15) >> 4;
    int nb = max(nbatch, __shfl_xor_sync(0xffffffffu, nbatch, 16));

    float denom = 0.f;
    float4 acc = make_float4(0.f, 0.f, 0.f, 0.f);

    for (int b = 0; b < nb; b++) {
        int idx = (b << 4) + sub;
        int   s  = 0;
        float ex = 0.f;
        if (idx < deg) {
            int2 p = __ldg(&g_pair[start + idx]);
            s  = p.x;
            ex = __int_as_float(p.y);
        }
        denom += ex;
        #pragma unroll
        for (int k = 0; k < 16; k++) {
            float exk = __shfl_sync(0xffffffffu, ex, k, 16);
            int   sk  = __shfl_sync(0xffffffffu, s,  k, 16);
            if (exk > 0.f) {
                uint2 hv = __ldg(&g_hsoft[(size_t)sk * 16 + sub]);
                __half2 h0 = *reinterpret_cast<__half2*>(&hv.x);
                __half2 h1 = *reinterpret_cast<__half2*>(&hv.y);
                float2 f0 = __half22float2(h0);
                float2 f1 = __half22float2(h1);
                acc.x += exk * f0.x;
                acc.y += exk * f0.y;
                acc.z += exk * f1.x;
                acc.w += exk * f1.y;
            }
        }
    }

    denom += __shfl_xor_sync(0xffffffffu, denom, 8, 16);
    denom += __shfl_xor_sync(0xffffffffu, denom, 4, 16);
    denom += __shfl_xor_sync(0xffffffffu, denom, 2, 16);
    denom += __shfl_xor_sync(0xffffffffu, denom, 1, 16);

    if (valid) {
        float inv = (deg > 0) ? __fdividef(1.f, denom) : 0.f;
        if (sub == 0) g_inv[node] = inv;
        float4 r;
        r.x = acc.x * inv; r.y = acc.y * inv;
        r.z = acc.z * inv; r.w = acc.w * inv;
        rst4[(size_t)node * 16 + sub] = r;
    }
}

__global__ void a_kernel(const int* __restrict__ dst,
                         const float* __restrict__ e,
                         float* __restrict__ a_out, int E) {
    int i = blockIdx.x * blockDim.x + threadIdx.x;
    if (i < E) a_out[i] = __expf(e[i]) * g_inv[dst[i]];
}

extern "C" void kernel_launch(void* const* d_in, const int* in_sizes, int n_in,
                              void* d_out, int out_size) {
    const int*   src  = (const int*)  d_in[1];
    const int*   dst  = (const int*)  d_in[2];
    const float* e    = (const float*)d_in[3];
    const float* soft = (const float*)d_in[4];
    const int E = in_sizes[1];
    const int N = in_sizes[4] / CLS;

    float* rst   = (float*)d_out;
    float* a_out = rst + (size_t)N * CLS;

    int nb   = (N + 255) / 256;
    int eb   = (E + 255) / 256;
    int eb8  = ((E + 7) / 8 + 255) / 256;
    int n4   = N * CLS / 4;
    int hb   = (n4 + 255) / 256;
    int sblk = (N + SCAN_B - 1) / SCAN_B;

    zero_counts_kernel<<<nb, 256>>>(N);
    tohalf_kernel<<<hb, 256>>>((const float4*)soft, n4);
    hist_kernel<<<eb8, 256>>>((const int4*)dst, E);
    reduce_blocks_kernel<<<sblk, SCAN_B>>>(N);
    scan_write_kernel<<<sblk, SCAN_B>>>(N, sblk);
    fill_kernel<<<eb8, 256>>>((const int4*)src, (const int4*)dst,
                              (const float4*)e, E);

    size_t tot = (size_t)N * 16;
    int gb = (int)((tot + 255) / 256);
    gather_kernel<<<gb, 256>>>((float4*)rst, N);

    a_kernel<<<eb, 256>>>(dst, e, a_out, E);
}